// round 8
// baseline (speedup 1.0000x reference)
#include <cuda_runtime.h>
#include <cuda_bf16.h>
#include <cstdint>

// ---------------------------------------------------------------------------
// CrossAttention, tensor-core mma.sync bf16 hi/lo (3-pass, fp32 accum).
// R8: GEMM mainloop — single barrier per K-iteration (bottom sync proved
// redundant) + 4-stage cp.async pipeline. 4 launches total.
// ---------------------------------------------------------------------------

#define B_SZ   32
#define N_SZ   1536
#define M_SZ   80
#define HEADS  8
#define CDIM   64
#define INNER  512
#define QD     320
#define KD     768
#define ROWS_Q (B_SZ * N_SZ)     // 49152
#define ROWS_K (B_SZ * M_SZ)     // 2560
#define SCALE  0.125f
#define LAMDA1 5.0f
#define BIGNEG (-3.402823466e38f)

// ---------------- scratch (device globals; allocation forbidden) -----------
__device__ __nv_bfloat16 g_xhi[ROWS_Q * QD],  g_xlo[ROWS_Q * QD];
__device__ __nv_bfloat16 g_khi[ROWS_K * KD],  g_klo[ROWS_K * KD];
__device__ __nv_bfloat16 g_vhi[ROWS_K * KD],  g_vlo[ROWS_K * KD];
__device__ __nv_bfloat16 g_wqhi[INNER * QD],  g_wqlo[INNER * QD];
__device__ __nv_bfloat16 g_wkhi[INNER * KD],  g_wklo[INNER * KD];
__device__ __nv_bfloat16 g_wvhi[INNER * KD],  g_wvlo[INNER * KD];
__device__ __nv_bfloat16 g_wohi[QD * INNER],  g_wolo[QD * INNER];
__device__ __nv_bfloat16 g_qhi [ROWS_Q * INNER], g_qlo [ROWS_Q * INNER];
__device__ __nv_bfloat16 g_kphi[ROWS_K * INNER], g_kplo[ROWS_K * INNER];
__device__ __nv_bfloat16 g_vthi[ROWS_K * INNER], g_vtlo[ROWS_K * INNER]; // [bh][c][m]
__device__ __nv_bfloat16 g_aohi[ROWS_Q * INNER], g_aolo[ROWS_Q * INNER];

// ---------------------------------------------------------------------------
// primitives
// ---------------------------------------------------------------------------
__device__ __forceinline__ uint32_t smem_u32(const void* p) {
    uint32_t a;
    asm("{ .reg .u64 t; cvta.to.shared.u64 t, %1; cvt.u32.u64 %0, t; }"
        : "=r"(a) : "l"(p));
    return a;
}
__device__ __forceinline__ void cp_async16(uint32_t dst, const void* src, uint32_t sz) {
    asm volatile("cp.async.cg.shared.global [%0], [%1], 16, %2;"
                 :: "r"(dst), "l"(src), "r"(sz));
}
__device__ __forceinline__ void cp_commit() { asm volatile("cp.async.commit_group;"); }
template <int N>
__device__ __forceinline__ void cp_wait() {
    asm volatile("cp.async.wait_group %0;" :: "n"(N));
}
__device__ __forceinline__ void ldmatrix_x4(uint32_t* r, uint32_t addr) {
    asm volatile("ldmatrix.sync.aligned.m8n8.x4.shared.b16 {%0,%1,%2,%3}, [%4];"
                 : "=r"(r[0]), "=r"(r[1]), "=r"(r[2]), "=r"(r[3]) : "r"(addr));
}
__device__ __forceinline__ void ldmatrix_x2(uint32_t* r, uint32_t addr) {
    asm volatile("ldmatrix.sync.aligned.m8n8.x2.shared.b16 {%0,%1}, [%2];"
                 : "=r"(r[0]), "=r"(r[1]) : "r"(addr));
}
__device__ __forceinline__ void mma16816(float* d, const uint32_t* a, const uint32_t* b) {
    asm volatile(
        "mma.sync.aligned.m16n8k16.row.col.f32.bf16.bf16.f32 "
        "{%0,%1,%2,%3}, {%4,%5,%6,%7}, {%8,%9}, {%0,%1,%2,%3};"
        : "+f"(d[0]), "+f"(d[1]), "+f"(d[2]), "+f"(d[3])
        : "r"(a[0]), "r"(a[1]), "r"(a[2]), "r"(a[3]), "r"(b[0]), "r"(b[1]));
}
__device__ __forceinline__ void split_store2(__nv_bfloat16* hi, __nv_bfloat16* lo,
                                             size_t idx, float v0, float v1) {
    __nv_bfloat16 h0 = __float2bfloat16(v0);
    __nv_bfloat16 h1 = __float2bfloat16(v1);
    *(__nv_bfloat162*)(hi + idx) = __halves2bfloat162(h0, h1);
    *(__nv_bfloat162*)(lo + idx) = __halves2bfloat162(
        __float2bfloat16(v0 - __bfloat162float(h0)),
        __float2bfloat16(v1 - __bfloat162float(h1)));
}
#define SWZ(off) ((off) ^ (((off) >> 3) & 0x70))

// ---------------------------------------------------------------------------
// mega-split: all 7 fp32 tensors -> bf16 hi/lo in one launch.
// ---------------------------------------------------------------------------
#define N4_X   (ROWS_Q * QD / 4)
#define N4_KEY (ROWS_K * KD / 4)
#define N4_VAL (ROWS_K * KD / 4)
#define N4_WQ  (INNER * QD / 4)
#define N4_WK  (INNER * KD / 4)
#define N4_WV  (INNER * KD / 4)
#define N4_WO  (QD * INNER / 4)
#define S1 (N4_X)
#define S2 (S1 + N4_KEY)
#define S3 (S2 + N4_VAL)
#define S4 (S3 + N4_WQ)
#define S5 (S4 + N4_WK)
#define S6 (S5 + N4_WV)
#define S7 (S6 + N4_WO)

__global__ void __launch_bounds__(256)
split_all(const float* __restrict__ x,   const float* __restrict__ key,
          const float* __restrict__ val, const float* __restrict__ wq,
          const float* __restrict__ wk,  const float* __restrict__ wv,
          const float* __restrict__ wo,
          __nv_bfloat16* __restrict__ xhi, __nv_bfloat16* __restrict__ xlo,
          __nv_bfloat16* __restrict__ khi, __nv_bfloat16* __restrict__ klo,
          __nv_bfloat16* __restrict__ vhi, __nv_bfloat16* __restrict__ vlo,
          __nv_bfloat16* __restrict__ wqhi, __nv_bfloat16* __restrict__ wqlo,
          __nv_bfloat16* __restrict__ wkhi, __nv_bfloat16* __restrict__ wklo,
          __nv_bfloat16* __restrict__ wvhi, __nv_bfloat16* __restrict__ wvlo,
          __nv_bfloat16* __restrict__ wohi, __nv_bfloat16* __restrict__ wolo)
{
    const int i = blockIdx.x * blockDim.x + threadIdx.x;
    if (i >= S7) return;

    const float* src; __nv_bfloat16 *hi, *lo; int off;
    if      (i < S1) { src = x;   hi = xhi;  lo = xlo;  off = i;      }
    else if (i < S2) { src = key; hi = khi;  lo = klo;  off = i - S1; }
    else if (i < S3) { src = val; hi = vhi;  lo = vlo;  off = i - S2; }
    else if (i < S4) { src = wq;  hi = wqhi; lo = wqlo; off = i - S3; }
    else if (i < S5) { src = wk;  hi = wkhi; lo = wklo; off = i - S4; }
    else if (i < S6) { src = wv;  hi = wvhi; lo = wvlo; off = i - S5; }
    else             { src = wo;  hi = wohi; lo = wolo; off = i - S6; }

    float4 v = ((const float4*)src)[off];
    split_store2(hi, lo, (size_t)off * 4,     v.x, v.y);
    split_store2(hi, lo, (size_t)off * 4 + 2, v.z, v.w);
}

// ---------------------------------------------------------------------------
// shared GEMM mainloop (BM=BN=128, BK=32, 4 warps 2x2, 64x64 warp tiles,
// 4-stage cp.async, ONE barrier per iteration, hi/lo 3-pass).
// Safety of single barrier: cp.async issued at iter `it` (after the top
// barrier) writes stage (it+3)%4 == (it-1)%4, whose reads happened in iter
// it-1; the top barrier of iter `it` orders those reads before these writes.
// ---------------------------------------------------------------------------
#define STAGE_B (128 * 40 * 2)   // 10240 bytes per operand per stage
#define NSTAGE  4
#define KCHUNK  32

struct GemmCore {
    uint32_t sbase;
    int tid, wid, lane, wm, wn;
    int g, r8, a_row_off, a_k_off, bx_row_off, bx_k_off;

    __device__ __forceinline__ void init(uint32_t sb, int t) {
        sbase = sb; tid = t;
        wid = t >> 5; lane = t & 31;
        wm = wid >> 1; wn = wid & 1;
        g = lane >> 3; r8 = lane & 7;
        a_row_off = (g & 1) * 8 + r8;
        a_k_off   = (g >> 1) * 16;
        bx_row_off = (g >> 1) * 8 + r8;
        bx_k_off   = (g & 1) * 16;
    }

    template <bool GUARD>
    __device__ __forceinline__ void load_stage(
        const __nv_bfloat16* Ahi, const __nv_bfloat16* Alo,
        const __nv_bfloat16* Bhi, const __nv_bfloat16* Blo,
        int rbase, int cbase, int cols, int K, int KC, int it, int stage)
    {
        const int seg = it / KC;
        const __nv_bfloat16* Ap = (seg == 2) ? Alo : Ahi;
        const __nv_bfloat16* Bp = (seg == 1) ? Blo : Bhi;
        const int kb = (it - seg * KC) * KCHUNK;
        const uint32_t abase = sbase + stage * 2 * STAGE_B;
        const uint32_t bbase = abase + STAGE_B;
#pragma unroll
        for (int t = 0; t < 4; t++) {
            const int task = t * 128 + tid;
            const int row  = task >> 2;
            const int ch   = task & 3;
            cp_async16(abase + row * 80 + ch * 16,
                       Ap + (size_t)(rbase + row) * K + kb + ch * 8, 16);
        }
#pragma unroll
        for (int t = 0; t < 4; t++) {
            const int task = t * 128 + tid;
            const int row  = task >> 2;
            const int ch   = task & 3;
            if (GUARD) {
                const int col   = cbase + row;
                const int valid = (col < cols);
                cp_async16(bbase + row * 80 + ch * 16,
                           Bp + (size_t)(valid ? col : 0) * K + kb + ch * 8,
                           valid ? 16u : 0u);
            } else {
                cp_async16(bbase + row * 80 + ch * 16,
                           Bp + (size_t)(cbase + row) * K + kb + ch * 8, 16);
            }
        }
        cp_commit();
    }

    template <bool GUARD>
    __device__ __forceinline__ void run(
        float acc[4][8][4],
        const __nv_bfloat16* Ahi, const __nv_bfloat16* Alo,
        const __nv_bfloat16* Bhi, const __nv_bfloat16* Blo,
        int rbase, int cbase, int cols, int K)
    {
        const int KC = K / KCHUNK;
        const int KT = 3 * KC;
        load_stage<GUARD>(Ahi, Alo, Bhi, Blo, rbase, cbase, cols, K, KC, 0, 0);
        load_stage<GUARD>(Ahi, Alo, Bhi, Blo, rbase, cbase, cols, K, KC, 1, 1);
        load_stage<GUARD>(Ahi, Alo, Bhi, Blo, rbase, cbase, cols, K, KC, 2, 2);

        for (int it = 0; it < KT; it++) {
            cp_wait<2>();
            __syncthreads();     // single barrier per iteration (see header)
            if (it + 3 < KT)
                load_stage<GUARD>(Ahi, Alo, Bhi, Blo, rbase, cbase, cols, K, KC,
                                  it + 3, (it + 3) & (NSTAGE - 1));
            else cp_commit();

            const int stage = it & (NSTAGE - 1);
            const uint32_t sA = sbase + stage * 2 * STAGE_B;
            const uint32_t sB = sA + STAGE_B;
#pragma unroll
            for (int s = 0; s < 2; s++) {
                uint32_t afrag[4][4];
                uint32_t bfrag[8][2];
#pragma unroll
                for (int i = 0; i < 4; i++)
                    ldmatrix_x4(afrag[i],
                        sA + (wm * 64 + i * 16 + a_row_off) * 80 + s * 32 + a_k_off);
#pragma unroll
                for (int jj = 0; jj < 4; jj++) {
                    uint32_t r[4];
                    ldmatrix_x4(r,
                        sB + (wn * 64 + jj * 16 + bx_row_off) * 80 + s * 32 + bx_k_off);
                    bfrag[jj * 2][0]     = r[0]; bfrag[jj * 2][1]     = r[1];
                    bfrag[jj * 2 + 1][0] = r[2]; bfrag[jj * 2 + 1][1] = r[3];
                }
#pragma unroll
                for (int i = 0; i < 4; i++)
#pragma unroll
                    for (int j = 0; j < 8; j++)
                        mma16816(acc[i][j], afrag[i], bfrag[j]);
            }
        }
    }
};

// ---------------------------------------------------------------------------
// merged projection kernel: blockIdx.z = 0:Q, 1:K, 2:V. cols = INNER always.
// ---------------------------------------------------------------------------
__global__ void __launch_bounds__(128, 2)
gemm_proj(const __nv_bfloat16* __restrict__ xhi, const __nv_bfloat16* __restrict__ xlo,
          const __nv_bfloat16* __restrict__ khi, const __nv_bfloat16* __restrict__ klo,
          const __nv_bfloat16* __restrict__ vhi, const __nv_bfloat16* __restrict__ vlo,
          const __nv_bfloat16* __restrict__ wqhi, const __nv_bfloat16* __restrict__ wqlo,
          const __nv_bfloat16* __restrict__ wkhi, const __nv_bfloat16* __restrict__ wklo,
          const __nv_bfloat16* __restrict__ wvhi, const __nv_bfloat16* __restrict__ wvlo,
          __nv_bfloat16* __restrict__ qhi, __nv_bfloat16* __restrict__ qlo,
          __nv_bfloat16* __restrict__ kphi, __nv_bfloat16* __restrict__ kplo,
          __nv_bfloat16* __restrict__ vthi, __nv_bfloat16* __restrict__ vtlo)
{
    const int z = blockIdx.z;
    if (z > 0 && blockIdx.y >= ROWS_K / 128) return;

    const __nv_bfloat16 *Ahi, *Alo, *Bhi, *Blo;
    __nv_bfloat16 *Chi, *Clo;
    int K;
    float ascale = 1.0f;
    if (z == 0) {
        Ahi = xhi; Alo = xlo; Bhi = wqhi; Blo = wqlo;
        Chi = qhi; Clo = qlo; K = QD; ascale = SCALE;
    } else if (z == 1) {
        Ahi = khi; Alo = klo; Bhi = wkhi; Blo = wklo;
        Chi = kphi; Clo = kplo; K = KD;
    } else {
        Ahi = vhi; Alo = vlo; Bhi = wvhi; Blo = wvlo;
        Chi = vthi; Clo = vtlo; K = KD;
    }

    extern __shared__ char smem[];
    GemmCore core;
    core.init(smem_u32(smem), threadIdx.x);

    const int rbase = blockIdx.y * 128;
    const int cbase = blockIdx.x * 128;

    float acc[4][8][4];
#pragma unroll
    for (int i = 0; i < 4; i++)
#pragma unroll
        for (int j = 0; j < 8; j++)
#pragma unroll
            for (int e = 0; e < 4; e++) acc[i][j][e] = 0.0f;

    core.run<false>(acc, Ahi, Alo, Bhi, Blo, rbase, cbase, INNER, K);

    const int qrow = core.lane >> 2;
    const int qcol = (core.lane & 3) * 2;
    if (z < 2) {
#pragma unroll
        for (int i = 0; i < 4; i++) {
            const int row0 = rbase + core.wm * 64 + i * 16 + qrow;
#pragma unroll
            for (int j = 0; j < 8; j++) {
                const int col0 = cbase + core.wn * 64 + j * 8 + qcol;
                split_store2(Chi, Clo, (size_t)row0 * INNER + col0,
                             acc[i][j][0] * ascale, acc[i][j][1] * ascale);
                split_store2(Chi, Clo, (size_t)(row0 + 8) * INNER + col0,
                             acc[i][j][2] * ascale, acc[i][j][3] * ascale);
            }
        }
    } else {
#pragma unroll
        for (int i = 0; i < 4; i++) {
            const int row0 = rbase + core.wm * 64 + i * 16 + qrow;
#pragma unroll
            for (int j = 0; j < 8; j++) {
                const int col0 = cbase + core.wn * 64 + j * 8 + qcol;
#pragma unroll
                for (int rr = 0; rr < 2; rr++) {
                    const int r = row0 + rr * 8;
                    const int bb = r / M_SZ;
                    const int m  = r - bb * M_SZ;
#pragma unroll
                    for (int cc = 0; cc < 2; cc++) {
                        const int col = col0 + cc;
                        const int idx = (bb * HEADS + (col >> 6)) * CDIM + (col & 63);
                        const float v = acc[i][j][rr * 2 + cc];
                        __nv_bfloat16 h = __float2bfloat16(v);
                        Chi[(size_t)idx * M_SZ + m] = h;
                        Clo[(size_t)idx * M_SZ + m] =
                            __float2bfloat16(v - __bfloat162float(h));
                    }
                }
            }
        }
    }
}

// ---------------------------------------------------------------------------
// output projection: out = ao @ Wo^T + bo (cols=320, guard needed)
// ---------------------------------------------------------------------------
__global__ void __launch_bounds__(128, 2)
gemm_out(const __nv_bfloat16* __restrict__ Ahi, const __nv_bfloat16* __restrict__ Alo,
         const __nv_bfloat16* __restrict__ Bhi, const __nv_bfloat16* __restrict__ Blo,
         const float* __restrict__ bias, float* __restrict__ Cf)
{
    extern __shared__ char smem[];
    GemmCore core;
    core.init(smem_u32(smem), threadIdx.x);

    const int rbase = blockIdx.y * 128;
    const int cbase = blockIdx.x * 128;

    float acc[4][8][4];
#pragma unroll
    for (int i = 0; i < 4; i++)
#pragma unroll
        for (int j = 0; j < 8; j++)
#pragma unroll
            for (int e = 0; e < 4; e++) acc[i][j][e] = 0.0f;

    core.run<true>(acc, Ahi, Alo, Bhi, Blo, rbase, cbase, QD, INNER);

    const int qrow = core.lane >> 2;
    const int qcol = (core.lane & 3) * 2;
#pragma unroll
    for (int i = 0; i < 4; i++) {
        const int row0 = rbase + core.wm * 64 + i * 16 + qrow;
#pragma unroll
        for (int j = 0; j < 8; j++) {
            const int col0 = cbase + core.wn * 64 + j * 8 + qcol;
            if (col0 >= QD) continue;
            const float b0 = bias[col0], b1 = bias[col0 + 1];
            *(float2*)(Cf + (size_t)row0 * QD + col0) =
                make_float2(acc[i][j][0] + b0, acc[i][j][1] + b1);
            *(float2*)(Cf + (size_t)(row0 + 8) * QD + col0) =
                make_float2(acc[i][j][2] + b0, acc[i][j][3] + b1);
        }
    }
}

// ---------------------------------------------------------------------------
// Fused attention (unchanged, validated): per (b,h,ntile=128):
// S = QK^T, mask + box bias, softmax, P SMEM-resident, O = P*Vt.
// ---------------------------------------------------------------------------
#define AT_QBUF  16384
#define AT_KBASE 32768
#define AT_KBUF  10240
#define AT_BOX   53248
#define AT_RED   94208
#define AT_P     32768
#define AT_PBUF  22528
#define AT_VBUF  11264
#define AT_SMEM  96576

__global__ void __launch_bounds__(128, 2)
attn_fused(const __nv_bfloat16* __restrict__ qhi, const __nv_bfloat16* __restrict__ qlo,
           const __nv_bfloat16* __restrict__ khi, const __nv_bfloat16* __restrict__ klo,
           const __nv_bfloat16* __restrict__ vthi, const __nv_bfloat16* __restrict__ vtlo,
           const int* __restrict__ mask, const float* __restrict__ box,
           __nv_bfloat16* __restrict__ aohi, __nv_bfloat16* __restrict__ aolo)
{
    extern __shared__ char smem[];
    const uint32_t sbase = smem_u32(smem);
    const int tid  = threadIdx.x;
    const int wid  = tid >> 5;
    const int lane = tid & 31;
    const int wr   = wid >> 1;
    const int wc   = wid & 1;
    const int bh   = blockIdx.y;
    const int b    = bh >> 3, h = bh & 7;
    const int nbase = blockIdx.x * 128;

    int* smask = (int*)(smem + AT_RED + 2048);
    if (tid < M_SZ) smask[tid] = mask[b * M_SZ + tid];

    const __nv_bfloat16* qsrc[2] = {qhi, qlo};
#pragma unroll
    for (int u = 0; u < 16; u++) {
        const int task = u * 128 + tid;
        const int buf  = task >> 10;
        const int rem  = task & 1023;
        const int row  = rem >> 3, ch = rem & 7;
        cp_async16(sbase + buf * AT_QBUF + SWZ(row * 128 + ch * 16),
                   qsrc[buf] + (size_t)(b * N_SZ + nbase + row) * INNER + h * CDIM + ch * 8, 16);
    }
    const __nv_bfloat16* ksrc[2] = {khi, klo};
#pragma unroll
    for (int u = 0; u < 10; u++) {
        const int task = u * 128 + tid;
        const int buf  = task >= 640;
        const int rem  = task - buf * 640;
        const int row  = rem >> 3, ch = rem & 7;
        cp_async16(sbase + AT_KBASE + buf * AT_KBUF + SWZ(row * 128 + ch * 16),
                   ksrc[buf] + (size_t)(b * M_SZ + row) * INNER + h * CDIM + ch * 8, 16);
    }
#pragma unroll
    for (int u = 0; u < 20; u++) {
        const int task = u * 128 + tid;
        const int row  = task / 20, ch = task - row * 20;
        cp_async16(sbase + AT_BOX + row * 320 + ch * 16,
                   box + (size_t)(b * N_SZ + nbase + row) * M_SZ + ch * 4, 16);
    }
    cp_commit();
    cp_wait<0>();
    __syncthreads();

    const int g  = lane >> 3;
    const int r8 = lane & 7;
    const int a_row_off = (g & 1) * 8 + r8;
    const int a_k_off   = (g >> 1) * 16;

    float acc[4][5][4];
#pragma unroll
    for (int i = 0; i < 4; i++)
#pragma unroll
        for (int j = 0; j < 5; j++)
#pragma unroll
            for (int e = 0; e < 4; e++) acc[i][j][e] = 0.0f;

#pragma unroll
    for (int p = 0; p < 3; p++) {
        const uint32_t qb = sbase + ((p == 2) ? AT_QBUF : 0);
        const uint32_t kb = sbase + AT_KBASE + ((p == 1) ? AT_KBUF : 0);
#pragma unroll
        for (int ks = 0; ks < 4; ks++) {
            uint32_t af[4][4], bf[5][2];
#pragma unroll
            for (int i = 0; i < 4; i++)
                ldmatrix_x4(af[i], qb + SWZ((wr * 64 + i * 16 + a_row_off) * 128
                                            + ks * 32 + a_k_off));
#pragma unroll
            for (int j = 0; j < 5; j++)
                ldmatrix_x2(bf[j], kb + SWZ((wc * 40 + j * 8 + r8) * 128
                                            + ks * 32 + (g & 1) * 16));
#pragma unroll
            for (int i = 0; i < 4; i++)
#pragma unroll
                for (int j = 0; j < 5; j++)
                    mma16816(acc[i][j], af[i], bf[j]);
        }
    }
    __syncthreads();

    const __nv_bfloat16* vsrc[2] = {vthi, vtlo};
#pragma unroll
    for (int u = 0; u < 10; u++) {
        const int task = u * 128 + tid;
        const int buf  = task >= 640;
        const int rem  = task - buf * 640;
        const int row  = rem / 10, ch = rem - row * 10;
        cp_async16(sbase + buf * AT_VBUF + row * 176 + ch * 16,
                   vsrc[buf] + ((size_t)bh * CDIM + row) * M_SZ + ch * 8, 16);
    }
    cp_commit();

    const float* boxS = (const float*)(smem + AT_BOX);
    const int qrow = lane >> 2;
    const int qcol = (lane & 3) * 2;
#pragma unroll
    for (int i = 0; i < 4; i++)
#pragma unroll
        for (int j = 0; j < 5; j++)
#pragma unroll
            for (int e = 0; e < 4; e++) {
                const int r = wr * 64 + i * 16 + qrow + (e >> 1) * 8;
                const int c = wc * 40 + j * 8 + qcol + (e & 1);
                acc[i][j][e] = smask[c]
                    ? acc[i][j][e] + LAMDA1 * boxS[r * 80 + c] : BIGNEG;
            }

    float* rmax = (float*)(smem + AT_RED);
    float* rsum = rmax + 256;
    float rm[4][2];
#pragma unroll
    for (int i = 0; i < 4; i++)
#pragma unroll
        for (int hf = 0; hf < 2; hf++) {
            float m = BIGNEG;
#pragma unroll
            for (int j = 0; j < 5; j++)
                m = fmaxf(m, fmaxf(acc[i][j][hf * 2], acc[i][j][hf * 2 + 1]));
            m = fmaxf(m, __shfl_xor_sync(0xffffffffu, m, 1));
            m = fmaxf(m, __shfl_xor_sync(0xffffffffu, m, 2));
            rm[i][hf] = m;
        }
    if ((lane & 3) == 0)
#pragma unroll
        for (int i = 0; i < 4; i++)
#pragma unroll
            for (int hf = 0; hf < 2; hf++)
                rmax[wc * 128 + wr * 64 + i * 16 + qrow + hf * 8] = rm[i][hf];
    __syncthreads();

    float rs[4][2];
#pragma unroll
    for (int i = 0; i < 4; i++)
#pragma unroll
        for (int hf = 0; hf < 2; hf++) {
            const int r = wr * 64 + i * 16 + qrow + hf * 8;
            const float m = fmaxf(rmax[r], rmax[128 + r]);
            float s = 0.0f;
#pragma unroll
            for (int j = 0; j < 5; j++) {
                acc[i][j][hf * 2]     = __expf(acc[i][j][hf * 2]     - m);
                acc[i][j][hf * 2 + 1] = __expf(acc[i][j][hf * 2 + 1] - m);
                s += acc[i][j][hf * 2] + acc[i][j][hf * 2 + 1];
            }
            s += __shfl_xor_sync(0xffffffffu, s, 1);
            s += __shfl_xor_sync(0xffffffffu, s, 2);
            rs[i][hf] = s;
        }
    if ((lane & 3) == 0)
#pragma unroll
        for (int i = 0; i < 4; i++)
#pragma unroll
            for (int hf = 0; hf < 2; hf++)
                rsum[wc * 128 + wr * 64 + i * 16 + qrow + hf * 8] = rs[i][hf];
    __syncthreads();

#pragma unroll
    for (int i = 0; i < 4; i++)
#pragma unroll
        for (int hf = 0; hf < 2; hf++) {
            const int r = wr * 64 + i * 16 + qrow + hf * 8;
            const float inv = 1.0f / (rsum[r] + rsum[128 + r]);
#pragma unroll
            for (int j = 0; j < 5; j++) {
                const int c0 = wc * 40 + j * 8 + qcol;
                const float p0 = acc[i][j][hf * 2] * inv;
                const float p1 = acc[i][j][hf * 2 + 1] * inv;
                __nv_bfloat16 h0 = __float2bfloat16(p0);
                __nv_bfloat16 h1 = __float2bfloat16(p1);
                *(__nv_bfloat162*)(smem + AT_P + r * 176 + c0 * 2) =
                    __halves2bfloat162(h0, h1);
                *(__nv_bfloat162*)(smem + AT_P + AT_PBUF + r * 176 + c0 * 2) =
                    __halves2bfloat162(
                        __float2bfloat16(p0 - __bfloat162float(h0)),
                        __float2bfloat16(p1 - __bfloat162float(h1)));
            }
        }
    cp_wait<0>();
    __syncthreads();

    float acc2[4][4][4];
#pragma unroll
    for (int i = 0; i < 4; i++)
#pragma unroll
        for (int j = 0; j < 4; j++)
#pragma unroll
            for (int e = 0; e < 4; e++) acc2[i][j][e] = 0.0f;

#pragma unroll
    for (int p = 0; p < 3; p++) {
        const uint32_t pb = sbase + AT_P + ((p == 2) ? AT_PBUF : 0);
        const uint32_t vb = sbase + ((p == 1) ? AT_VBUF : 0);
#pragma unroll
        for (int ks = 0; ks < 5; ks++) {
            uint32_t af[4][4], bf[4][2];
#pragma unroll
            for (int i = 0; i < 4; i++)
                ldmatrix_x4(af[i], pb + (wr * 64 + i * 16 + a_row_off) * 176
                                      + ks * 32 + a_k_off);
#pragma unroll
            for (int j = 0; j < 4; j++)
                ldmatrix_x2(bf[j], vb + (wc * 32 + j * 8 + r8) * 176
                                      + ks * 32 + (g & 1) * 16);
#pragma unroll
            for (int i = 0; i < 4; i++)
#pragma unroll
                for (int j = 0; j < 4; j++)
                    mma16816(acc2[i][j], af[i], bf[j]);
        }
    }

#pragma unroll
    for (int i = 0; i < 4; i++) {
        const int n0 = nbase + wr * 64 + i * 16 + qrow;
#pragma unroll
        for (int j = 0; j < 4; j++) {
            const int c0 = wc * 32 + j * 8 + qcol;
            const size_t i0 = (size_t)(b * N_SZ + n0) * INNER + h * CDIM + c0;
            split_store2(aohi, aolo, i0,                     acc2[i][j][0], acc2[i][j][1]);
            split_store2(aohi, aolo, i0 + (size_t)8 * INNER, acc2[i][j][2], acc2[i][j][3]);
        }
    }
}

// ---------------------------------------------------------------------------
// Launch (4 kernels total)
// ---------------------------------------------------------------------------
extern "C" void kernel_launch(void* const* d_in, const int* in_sizes, int n_in,
                              void* d_out, int out_size)
{
    const float* x    = (const float*)d_in[0];
    const float* key  = (const float*)d_in[1];
    const float* val  = (const float*)d_in[2];
    const int*   mask = (const int*)d_in[3];
    const float* box  = (const float*)d_in[4];
    // d_in[5] road map: softmax-invariant, unused
    const float* Wq   = (const float*)d_in[6];
    const float* Wk   = (const float*)d_in[7];
    const float* Wv   = (const float*)d_in[8];
    const float* Wo   = (const float*)d_in[9];
    const float* bo   = (const float*)d_in[10];
    float*       out  = (float*)d_out;

    __nv_bfloat16 *xhi, *xlo, *khi, *klo, *vhi, *vlo;
    __nv_bfloat16 *wqhi, *wqlo, *wkhi, *wklo, *wvhi, *wvlo, *wohi, *wolo;
    __nv_bfloat16 *qhi, *qlo, *kphi, *kplo, *vthi, *vtlo, *aohi, *aolo;
    cudaGetSymbolAddress((void**)&xhi, g_xhi);   cudaGetSymbolAddress((void**)&xlo, g_xlo);
    cudaGetSymbolAddress((void**)&khi, g_khi);   cudaGetSymbolAddress((void**)&klo, g_klo);
    cudaGetSymbolAddress((void**)&vhi, g_vhi);   cudaGetSymbolAddress((void**)&vlo, g_vlo);
    cudaGetSymbolAddress((void**)&wqhi, g_wqhi); cudaGetSymbolAddress((void**)&wqlo, g_wqlo);
    cudaGetSymbolAddress((void**)&wkhi, g_wkhi); cudaGetSymbolAddress((void**)&wklo, g_wklo);
    cudaGetSymbolAddress((void**)&wvhi, g_wvhi); cudaGetSymbolAddress((void**)&wvlo, g_wvlo);
    cudaGetSymbolAddress((void**)&wohi, g_wohi); cudaGetSymbolAddress((void**)&wolo, g_wolo);
    cudaGetSymbolAddress((void**)&qhi, g_qhi);   cudaGetSymbolAddress((void**)&qlo, g_qlo);
    cudaGetSymbolAddress((void**)&kphi, g_kphi); cudaGetSymbolAddress((void**)&kplo, g_kplo);
    cudaGetSymbolAddress((void**)&vthi, g_vthi); cudaGetSymbolAddress((void**)&vtlo, g_vtlo);
    cudaGetSymbolAddress((void**)&aohi, g_aohi); cudaGetSymbolAddress((void**)&aolo, g_aolo);

    constexpr int SMEM_G = NSTAGE * 2 * STAGE_B;   // 81920
    cudaFuncSetAttribute(gemm_proj, cudaFuncAttributeMaxDynamicSharedMemorySize, SMEM_G);
    cudaFuncSetAttribute(gemm_out,  cudaFuncAttributeMaxDynamicSharedMemorySize, SMEM_G);
    cudaFuncSetAttribute(attn_fused, cudaFuncAttributeMaxDynamicSharedMemorySize, AT_SMEM);

    // 1) all splits in one launch
    split_all<<<(S7 + 255) / 256, 256>>>(
        x, key, val, Wq, Wk, Wv, Wo,
        xhi, xlo, khi, klo, vhi, vlo,
        wqhi, wqlo, wkhi, wklo, wvhi, wvlo, wohi, wolo);

    // 2) all three projections in one launch (z: 0=Q, 1=K, 2=V)
    gemm_proj<<<dim3(INNER / 128, ROWS_Q / 128, 3), 128, SMEM_G>>>(
        xhi, xlo, khi, klo, vhi, vlo,
        wqhi, wqlo, wkhi, wklo, wvhi, wvlo,
        qhi, qlo, kphi, kplo, vthi, vtlo);

    // 3) fused attention
    attn_fused<<<dim3(N_SZ / 128, B_SZ * HEADS), 128, AT_SMEM>>>(
        qhi, qlo, kphi, kplo, vthi, vtlo, mask, box, aohi, aolo);

    // 4) output projection + bias
    gemm_out<<<dim3((QD + 127) / 128, ROWS_Q / 128), 128, SMEM_G>>>(
        aohi, aolo, wohi, wolo, bo, out);
}

// round 9
// speedup vs baseline: 1.3432x; 1.3432x over previous
#include <cuda_runtime.h>
#include <cuda_bf16.h>
#include <cuda_fp16.h>
#include <cstdint>

// ---------------------------------------------------------------------------
// CrossAttention. R9: projections + out-proj on fp16 2-pass mma.sync
// (A hi-only, W hi + lo*2^12; acc = A*Wlo' ; acc *= 2^-12 ; acc += A*Whi).
// Fused attention stays bf16 hi/lo 3-pass (validated).
// ---------------------------------------------------------------------------

#define B_SZ   32
#define N_SZ   1536
#define M_SZ   80
#define HEADS  8
#define CDIM   64
#define INNER  512
#define QD     320
#define KD     768
#define ROWS_Q (B_SZ * N_SZ)     // 49152
#define ROWS_K (B_SZ * M_SZ)     // 2560
#define SCALE  0.125f
#define LAMDA1 5.0f
#define BIGNEG (-3.402823466e38f)
#define LOSCL  4096.0f
#define LOINV  (1.0f / 4096.0f)

// ---------------- scratch (device globals; allocation forbidden) -----------
__device__ __half g_xh[ROWS_Q * QD];
__device__ __half g_kh[ROWS_K * KD];
__device__ __half g_vh[ROWS_K * KD];
__device__ __half g_wqh[INNER * QD], g_wql[INNER * QD];
__device__ __half g_wkh[INNER * KD], g_wkl[INNER * KD];
__device__ __half g_wvh[INNER * KD], g_wvl[INNER * KD];
__device__ __half g_woh[QD * INNER], g_wol[QD * INNER];
__device__ __nv_bfloat16 g_qhi [ROWS_Q * INNER], g_qlo [ROWS_Q * INNER];
__device__ __nv_bfloat16 g_kphi[ROWS_K * INNER], g_kplo[ROWS_K * INNER];
__device__ __nv_bfloat16 g_vthi[ROWS_K * INNER], g_vtlo[ROWS_K * INNER]; // [bh][c][m]
__device__ __half g_aoh[ROWS_Q * INNER];

// ---------------------------------------------------------------------------
// primitives
// ---------------------------------------------------------------------------
__device__ __forceinline__ uint32_t smem_u32(const void* p) {
    uint32_t a;
    asm("{ .reg .u64 t; cvta.to.shared.u64 t, %1; cvt.u32.u64 %0, t; }"
        : "=r"(a) : "l"(p));
    return a;
}
__device__ __forceinline__ void cp_async16(uint32_t dst, const void* src, uint32_t sz) {
    asm volatile("cp.async.cg.shared.global [%0], [%1], 16, %2;"
                 :: "r"(dst), "l"(src), "r"(sz));
}
__device__ __forceinline__ void cp_commit() { asm volatile("cp.async.commit_group;"); }
template <int N>
__device__ __forceinline__ void cp_wait() {
    asm volatile("cp.async.wait_group %0;" :: "n"(N));
}
__device__ __forceinline__ void ldmatrix_x4(uint32_t* r, uint32_t addr) {
    asm volatile("ldmatrix.sync.aligned.m8n8.x4.shared.b16 {%0,%1,%2,%3}, [%4];"
                 : "=r"(r[0]), "=r"(r[1]), "=r"(r[2]), "=r"(r[3]) : "r"(addr));
}
__device__ __forceinline__ void ldmatrix_x2(uint32_t* r, uint32_t addr) {
    asm volatile("ldmatrix.sync.aligned.m8n8.x2.shared.b16 {%0,%1}, [%2];"
                 : "=r"(r[0]), "=r"(r[1]) : "r"(addr));
}
// bf16 mma (attention)
__device__ __forceinline__ void mma16816(float* d, const uint32_t* a, const uint32_t* b) {
    asm volatile(
        "mma.sync.aligned.m16n8k16.row.col.f32.bf16.bf16.f32 "
        "{%0,%1,%2,%3}, {%4,%5,%6,%7}, {%8,%9}, {%0,%1,%2,%3};"
        : "+f"(d[0]), "+f"(d[1]), "+f"(d[2]), "+f"(d[3])
        : "r"(a[0]), "r"(a[1]), "r"(a[2]), "r"(a[3]), "r"(b[0]), "r"(b[1]));
}
// fp16 mma (projections / out)
__device__ __forceinline__ void mma16816h(float* d, const uint32_t* a, const uint32_t* b) {
    asm volatile(
        "mma.sync.aligned.m16n8k16.row.col.f32.f16.f16.f32 "
        "{%0,%1,%2,%3}, {%4,%5,%6,%7}, {%8,%9}, {%0,%1,%2,%3};"
        : "+f"(d[0]), "+f"(d[1]), "+f"(d[2]), "+f"(d[3])
        : "r"(a[0]), "r"(a[1]), "r"(a[2]), "r"(a[3]), "r"(b[0]), "r"(b[1]));
}
__device__ __forceinline__ void split_store2(__nv_bfloat16* hi, __nv_bfloat16* lo,
                                             size_t idx, float v0, float v1) {
    __nv_bfloat16 h0 = __float2bfloat16(v0);
    __nv_bfloat16 h1 = __float2bfloat16(v1);
    *(__nv_bfloat162*)(hi + idx) = __halves2bfloat162(h0, h1);
    *(__nv_bfloat162*)(lo + idx) = __halves2bfloat162(
        __float2bfloat16(v0 - __bfloat162float(h0)),
        __float2bfloat16(v1 - __bfloat162float(h1)));
}
__device__ __forceinline__ void h_store2(__half* hi, size_t idx, float a, float b) {
    *(__half2*)(hi + idx) = __floats2half2_rn(a, b);
}
__device__ __forceinline__ void hl_store2(__half* hi, __half* lo, size_t idx,
                                          float a, float b) {
    __half ha = __float2half_rn(a), hb = __float2half_rn(b);
    *(__half2*)(hi + idx) = __halves2half2(ha, hb);
    *(__half2*)(lo + idx) = __floats2half2_rn((a - __half2float(ha)) * LOSCL,
                                              (b - __half2float(hb)) * LOSCL);
}
#define SWZ(off) ((off) ^ (((off) >> 3) & 0x70))

// ---------------------------------------------------------------------------
// mega-split: activations -> fp16 hi only; weights -> fp16 hi + lo*2^12.
// ---------------------------------------------------------------------------
#define N4_X   (ROWS_Q * QD / 4)
#define N4_KEY (ROWS_K * KD / 4)
#define N4_VAL (ROWS_K * KD / 4)
#define N4_WQ  (INNER * QD / 4)
#define N4_WK  (INNER * KD / 4)
#define N4_WV  (INNER * KD / 4)
#define N4_WO  (QD * INNER / 4)
#define S1 (N4_X)
#define S2 (S1 + N4_KEY)
#define S3 (S2 + N4_VAL)
#define S4 (S3 + N4_WQ)
#define S5 (S4 + N4_WK)
#define S6 (S5 + N4_WV)
#define S7 (S6 + N4_WO)

__global__ void __launch_bounds__(256)
split_all(const float* __restrict__ x,   const float* __restrict__ key,
          const float* __restrict__ val, const float* __restrict__ wq,
          const float* __restrict__ wk,  const float* __restrict__ wv,
          const float* __restrict__ wo,
          __half* __restrict__ xh, __half* __restrict__ kh, __half* __restrict__ vh,
          __half* __restrict__ wqh, __half* __restrict__ wql,
          __half* __restrict__ wkh, __half* __restrict__ wkl,
          __half* __restrict__ wvh, __half* __restrict__ wvl,
          __half* __restrict__ woh, __half* __restrict__ wol)
{
    const int i = blockIdx.x * blockDim.x + threadIdx.x;
    if (i >= S7) return;

    if (i < S3) {               // activations: fp16 hi only
        const float* src; __half* hi; int off;
        if      (i < S1) { src = x;   hi = xh; off = i;      }
        else if (i < S2) { src = key; hi = kh; off = i - S1; }
        else             { src = val; hi = vh; off = i - S2; }
        float4 v = ((const float4*)src)[off];
        h_store2(hi, (size_t)off * 4,     v.x, v.y);
        h_store2(hi, (size_t)off * 4 + 2, v.z, v.w);
    } else {                    // weights: fp16 hi + scaled lo
        const float* src; __half *hi, *lo; int off;
        if      (i < S4) { src = wq; hi = wqh; lo = wql; off = i - S3; }
        else if (i < S5) { src = wk; hi = wkh; lo = wkl; off = i - S4; }
        else if (i < S6) { src = wv; hi = wvh; lo = wvl; off = i - S5; }
        else             { src = wo; hi = woh; lo = wol; off = i - S6; }
        float4 v = ((const float4*)src)[off];
        hl_store2(hi, lo, (size_t)off * 4,     v.x, v.y);
        hl_store2(hi, lo, (size_t)off * 4 + 2, v.z, v.w);
    }
}

// ---------------------------------------------------------------------------
// fp16 2-pass GEMM core (BM=BN=128, BK=32, 4 warps 2x2, 64x64 warp tiles,
// 4-stage cp.async, single barrier per iter).
// Pass 1 (it < KC): acc += A*Blo'  ; at it==KC: acc *= 2^-12 ;
// Pass 2 (it >= KC): acc += A*Bhi.
// ---------------------------------------------------------------------------
#define STAGE_B (128 * 40 * 2)   // 10240 bytes per operand per stage
#define NSTAGE  4
#define KCHUNK  32

struct GemmCore {
    uint32_t sbase;
    int tid, wid, lane, wm, wn;
    int g, r8, a_row_off, a_k_off, bx_row_off, bx_k_off;

    __device__ __forceinline__ void init(uint32_t sb, int t) {
        sbase = sb; tid = t;
        wid = t >> 5; lane = t & 31;
        wm = wid >> 1; wn = wid & 1;
        g = lane >> 3; r8 = lane & 7;
        a_row_off = (g & 1) * 8 + r8;
        a_k_off   = (g >> 1) * 16;
        bx_row_off = (g >> 1) * 8 + r8;
        bx_k_off   = (g & 1) * 16;
    }

    template <bool GUARD>
    __device__ __forceinline__ void load_stage(
        const __half* A, const __half* Bhi, const __half* Blo,
        int rbase, int cbase, int cols, int K, int KC, int it, int stage)
    {
        const __half* Bp = (it < KC) ? Blo : Bhi;   // corrections first
        const int kb = ((it < KC) ? it : it - KC) * KCHUNK;
        const uint32_t abase = sbase + stage * 2 * STAGE_B;
        const uint32_t bbase = abase + STAGE_B;
#pragma unroll
        for (int t = 0; t < 4; t++) {
            const int task = t * 128 + tid;
            const int row  = task >> 2;
            const int ch   = task & 3;
            cp_async16(abase + row * 80 + ch * 16,
                       A + (size_t)(rbase + row) * K + kb + ch * 8, 16);
        }
#pragma unroll
        for (int t = 0; t < 4; t++) {
            const int task = t * 128 + tid;
            const int row  = task >> 2;
            const int ch   = task & 3;
            if (GUARD) {
                const int col   = cbase + row;
                const int valid = (col < cols);
                cp_async16(bbase + row * 80 + ch * 16,
                           Bp + (size_t)(valid ? col : 0) * K + kb + ch * 8,
                           valid ? 16u : 0u);
            } else {
                cp_async16(bbase + row * 80 + ch * 16,
                           Bp + (size_t)(cbase + row) * K + kb + ch * 8, 16);
            }
        }
        cp_commit();
    }

    template <bool GUARD>
    __device__ __forceinline__ void run(
        float acc[4][8][4],
        const __half* A, const __half* Bhi, const __half* Blo,
        int rbase, int cbase, int cols, int K)
    {
        const int KC = K / KCHUNK;
        const int KT = 2 * KC;
        load_stage<GUARD>(A, Bhi, Blo, rbase, cbase, cols, K, KC, 0, 0);
        load_stage<GUARD>(A, Bhi, Blo, rbase, cbase, cols, K, KC, 1, 1);
        load_stage<GUARD>(A, Bhi, Blo, rbase, cbase, cols, K, KC, 2, 2);

        for (int it = 0; it < KT; it++) {
            cp_wait<2>();
            __syncthreads();
            if (it + 3 < KT)
                load_stage<GUARD>(A, Bhi, Blo, rbase, cbase, cols, K, KC,
                                  it + 3, (it + 3) & (NSTAGE - 1));
            else cp_commit();

            if (it == KC) {       // end of correction pass: downscale
#pragma unroll
                for (int i = 0; i < 4; i++)
#pragma unroll
                    for (int j = 0; j < 8; j++)
#pragma unroll
                        for (int e = 0; e < 4; e++) acc[i][j][e] *= LOINV;
            }

            const int stage = it & (NSTAGE - 1);
            const uint32_t sA = sbase + stage * 2 * STAGE_B;
            const uint32_t sB = sA + STAGE_B;
#pragma unroll
            for (int s = 0; s < 2; s++) {
                uint32_t afrag[4][4];
                uint32_t bfrag[8][2];
#pragma unroll
                for (int i = 0; i < 4; i++)
                    ldmatrix_x4(afrag[i],
                        sA + (wm * 64 + i * 16 + a_row_off) * 80 + s * 32 + a_k_off);
#pragma unroll
                for (int jj = 0; jj < 4; jj++) {
                    uint32_t r[4];
                    ldmatrix_x4(r,
                        sB + (wn * 64 + jj * 16 + bx_row_off) * 80 + s * 32 + bx_k_off);
                    bfrag[jj * 2][0]     = r[0]; bfrag[jj * 2][1]     = r[1];
                    bfrag[jj * 2 + 1][0] = r[2]; bfrag[jj * 2 + 1][1] = r[3];
                }
#pragma unroll
                for (int i = 0; i < 4; i++)
#pragma unroll
                    for (int j = 0; j < 8; j++)
                        mma16816h(acc[i][j], afrag[i], bfrag[j]);
            }
        }
    }
};

// ---------------------------------------------------------------------------
// merged projection kernel: blockIdx.z = 0:Q, 1:K, 2:V. cols = INNER.
// Outputs stay bf16 hi/lo (attention kernel unchanged).
// ---------------------------------------------------------------------------
__global__ void __launch_bounds__(128, 2)
gemm_proj(const __half* __restrict__ xh, const __half* __restrict__ kh,
          const __half* __restrict__ vh,
          const __half* __restrict__ wqh, const __half* __restrict__ wql,
          const __half* __restrict__ wkh, const __half* __restrict__ wkl,
          const __half* __restrict__ wvh, const __half* __restrict__ wvl,
          __nv_bfloat16* __restrict__ qhi, __nv_bfloat16* __restrict__ qlo,
          __nv_bfloat16* __restrict__ kphi, __nv_bfloat16* __restrict__ kplo,
          __nv_bfloat16* __restrict__ vthi, __nv_bfloat16* __restrict__ vtlo)
{
    const int z = blockIdx.z;
    if (z > 0 && blockIdx.y >= ROWS_K / 128) return;

    const __half *A, *Bhi, *Blo;
    __nv_bfloat16 *Chi, *Clo;
    int K;
    float ascale = 1.0f;
    if (z == 0) {
        A = xh; Bhi = wqh; Blo = wql; Chi = qhi; Clo = qlo; K = QD; ascale = SCALE;
    } else if (z == 1) {
        A = kh; Bhi = wkh; Blo = wkl; Chi = kphi; Clo = kplo; K = KD;
    } else {
        A = vh; Bhi = wvh; Blo = wvl; Chi = vthi; Clo = vtlo; K = KD;
    }

    extern __shared__ char smem[];
    GemmCore core;
    core.init(smem_u32(smem), threadIdx.x);

    const int rbase = blockIdx.y * 128;
    const int cbase = blockIdx.x * 128;

    float acc[4][8][4];
#pragma unroll
    for (int i = 0; i < 4; i++)
#pragma unroll
        for (int j = 0; j < 8; j++)
#pragma unroll
            for (int e = 0; e < 4; e++) acc[i][j][e] = 0.0f;

    core.run<false>(acc, A, Bhi, Blo, rbase, cbase, INNER, K);

    const int qrow = core.lane >> 2;
    const int qcol = (core.lane & 3) * 2;
    if (z < 2) {
#pragma unroll
        for (int i = 0; i < 4; i++) {
            const int row0 = rbase + core.wm * 64 + i * 16 + qrow;
#pragma unroll
            for (int j = 0; j < 8; j++) {
                const int col0 = cbase + core.wn * 64 + j * 8 + qcol;
                split_store2(Chi, Clo, (size_t)row0 * INNER + col0,
                             acc[i][j][0] * ascale, acc[i][j][1] * ascale);
                split_store2(Chi, Clo, (size_t)(row0 + 8) * INNER + col0,
                             acc[i][j][2] * ascale, acc[i][j][3] * ascale);
            }
        }
    } else {
#pragma unroll
        for (int i = 0; i < 4; i++) {
            const int row0 = rbase + core.wm * 64 + i * 16 + qrow;
#pragma unroll
            for (int j = 0; j < 8; j++) {
                const int col0 = cbase + core.wn * 64 + j * 8 + qcol;
#pragma unroll
                for (int rr = 0; rr < 2; rr++) {
                    const int r = row0 + rr * 8;
                    const int bb = r / M_SZ;
                    const int m  = r - bb * M_SZ;
#pragma unroll
                    for (int cc = 0; cc < 2; cc++) {
                        const int col = col0 + cc;
                        const int idx = (bb * HEADS + (col >> 6)) * CDIM + (col & 63);
                        const float v = acc[i][j][rr * 2 + cc];
                        __nv_bfloat16 h = __float2bfloat16(v);
                        Chi[(size_t)idx * M_SZ + m] = h;
                        Clo[(size_t)idx * M_SZ + m] =
                            __float2bfloat16(v - __bfloat162float(h));
                    }
                }
            }
        }
    }
}

// ---------------------------------------------------------------------------
// output projection: out = ao @ Wo^T + bo (cols=320, guard needed)
// ---------------------------------------------------------------------------
__global__ void __launch_bounds__(128, 2)
gemm_out(const __half* __restrict__ A,
         const __half* __restrict__ Bhi, const __half* __restrict__ Blo,
         const float* __restrict__ bias, float* __restrict__ Cf)
{
    extern __shared__ char smem[];
    GemmCore core;
    core.init(smem_u32(smem), threadIdx.x);

    const int rbase = blockIdx.y * 128;
    const int cbase = blockIdx.x * 128;

    float acc[4][8][4];
#pragma unroll
    for (int i = 0; i < 4; i++)
#pragma unroll
        for (int j = 0; j < 8; j++)
#pragma unroll
            for (int e = 0; e < 4; e++) acc[i][j][e] = 0.0f;

    core.run<true>(acc, A, Bhi, Blo, rbase, cbase, QD, INNER);

    const int qrow = core.lane >> 2;
    const int qcol = (core.lane & 3) * 2;
#pragma unroll
    for (int i = 0; i < 4; i++) {
        const int row0 = rbase + core.wm * 64 + i * 16 + qrow;
#pragma unroll
        for (int j = 0; j < 8; j++) {
            const int col0 = cbase + core.wn * 64 + j * 8 + qcol;
            if (col0 >= QD) continue;
            const float b0 = bias[col0], b1 = bias[col0 + 1];
            *(float2*)(Cf + (size_t)row0 * QD + col0) =
                make_float2(acc[i][j][0] + b0, acc[i][j][1] + b1);
            *(float2*)(Cf + (size_t)(row0 + 8) * QD + col0) =
                make_float2(acc[i][j][2] + b0, acc[i][j][3] + b1);
        }
    }
}

// ---------------------------------------------------------------------------
// Fused attention (bf16 hi/lo 3-pass, validated). Output: ao as fp16 hi-only.
// ---------------------------------------------------------------------------
#define AT_QBUF  16384
#define AT_KBASE 32768
#define AT_KBUF  10240
#define AT_BOX   53248
#define AT_RED   94208
#define AT_P     32768
#define AT_PBUF  22528
#define AT_VBUF  11264
#define AT_SMEM  96576

__global__ void __launch_bounds__(128, 2)
attn_fused(const __nv_bfloat16* __restrict__ qhi, const __nv_bfloat16* __restrict__ qlo,
           const __nv_bfloat16* __restrict__ khi, const __nv_bfloat16* __restrict__ klo,
           const __nv_bfloat16* __restrict__ vthi, const __nv_bfloat16* __restrict__ vtlo,
           const int* __restrict__ mask, const float* __restrict__ box,
           __half* __restrict__ aoh)
{
    extern __shared__ char smem[];
    const uint32_t sbase = smem_u32(smem);
    const int tid  = threadIdx.x;
    const int wid  = tid >> 5;
    const int lane = tid & 31;
    const int wr   = wid >> 1;
    const int wc   = wid & 1;
    const int bh   = blockIdx.y;
    const int b    = bh >> 3, h = bh & 7;
    const int nbase = blockIdx.x * 128;

    int* smask = (int*)(smem + AT_RED + 2048);
    if (tid < M_SZ) smask[tid] = mask[b * M_SZ + tid];

    const __nv_bfloat16* qsrc[2] = {qhi, qlo};
#pragma unroll
    for (int u = 0; u < 16; u++) {
        const int task = u * 128 + tid;
        const int buf  = task >> 10;
        const int rem  = task & 1023;
        const int row  = rem >> 3, ch = rem & 7;
        cp_async16(sbase + buf * AT_QBUF + SWZ(row * 128 + ch * 16),
                   qsrc[buf] + (size_t)(b * N_SZ + nbase + row) * INNER + h * CDIM + ch * 8, 16);
    }
    const __nv_bfloat16* ksrc[2] = {khi, klo};
#pragma unroll
    for (int u = 0; u < 10; u++) {
        const int task = u * 128 + tid;
        const int buf  = task >= 640;
        const int rem  = task - buf * 640;
        const int row  = rem >> 3, ch = rem & 7;
        cp_async16(sbase + AT_KBASE + buf * AT_KBUF + SWZ(row * 128 + ch * 16),
                   ksrc[buf] + (size_t)(b * M_SZ + row) * INNER + h * CDIM + ch * 8, 16);
    }
#pragma unroll
    for (int u = 0; u < 20; u++) {
        const int task = u * 128 + tid;
        const int row  = task / 20, ch = task - row * 20;
        cp_async16(sbase + AT_BOX + row * 320 + ch * 16,
                   box + (size_t)(b * N_SZ + nbase + row) * M_SZ + ch * 4, 16);
    }
    cp_commit();
    cp_wait<0>();
    __syncthreads();

    const int g  = lane >> 3;
    const int r8 = lane & 7;
    const int a_row_off = (g & 1) * 8 + r8;
    const int a_k_off   = (g >> 1) * 16;

    float acc[4][5][4];
#pragma unroll
    for (int i = 0; i < 4; i++)
#pragma unroll
        for (int j = 0; j < 5; j++)
#pragma unroll
            for (int e = 0; e < 4; e++) acc[i][j][e] = 0.0f;

#pragma unroll
    for (int p = 0; p < 3; p++) {
        const uint32_t qb = sbase + ((p == 2) ? AT_QBUF : 0);
        const uint32_t kb = sbase + AT_KBASE + ((p == 1) ? AT_KBUF : 0);
#pragma unroll
        for (int ks = 0; ks < 4; ks++) {
            uint32_t af[4][4], bf[5][2];
#pragma unroll
            for (int i = 0; i < 4; i++)
                ldmatrix_x4(af[i], qb + SWZ((wr * 64 + i * 16 + a_row_off) * 128
                                            + ks * 32 + a_k_off));
#pragma unroll
            for (int j = 0; j < 5; j++)
                ldmatrix_x2(bf[j], kb + SWZ((wc * 40 + j * 8 + r8) * 128
                                            + ks * 32 + (g & 1) * 16));
#pragma unroll
            for (int i = 0; i < 4; i++)
#pragma unroll
                for (int j = 0; j < 5; j++)
                    mma16816(acc[i][j], af[i], bf[j]);
        }
    }
    __syncthreads();

    const __nv_bfloat16* vsrc[2] = {vthi, vtlo};
#pragma unroll
    for (int u = 0; u < 10; u++) {
        const int task = u * 128 + tid;
        const int buf  = task >= 640;
        const int rem  = task - buf * 640;
        const int row  = rem / 10, ch = rem - row * 10;
        cp_async16(sbase + buf * AT_VBUF + row * 176 + ch * 16,
                   vsrc[buf] + ((size_t)bh * CDIM + row) * M_SZ + ch * 8, 16);
    }
    cp_commit();

    const float* boxS = (const float*)(smem + AT_BOX);
    const int qrow = lane >> 2;
    const int qcol = (lane & 3) * 2;
#pragma unroll
    for (int i = 0; i < 4; i++)
#pragma unroll
        for (int j = 0; j < 5; j++)
#pragma unroll
            for (int e = 0; e < 4; e++) {
                const int r = wr * 64 + i * 16 + qrow + (e >> 1) * 8;
                const int c = wc * 40 + j * 8 + qcol + (e & 1);
                acc[i][j][e] = smask[c]
                    ? acc[i][j][e] + LAMDA1 * boxS[r * 80 + c] : BIGNEG;
            }

    float* rmax = (float*)(smem + AT_RED);
    float* rsum = rmax + 256;
    float rm[4][2];
#pragma unroll
    for (int i = 0; i < 4; i++)
#pragma unroll
        for (int hf = 0; hf < 2; hf++) {
            float m = BIGNEG;
#pragma unroll
            for (int j = 0; j < 5; j++)
                m = fmaxf(m, fmaxf(acc[i][j][hf * 2], acc[i][j][hf * 2 + 1]));
            m = fmaxf(m, __shfl_xor_sync(0xffffffffu, m, 1));
            m = fmaxf(m, __shfl_xor_sync(0xffffffffu, m, 2));
            rm[i][hf] = m;
        }
    if ((lane & 3) == 0)
#pragma unroll
        for (int i = 0; i < 4; i++)
#pragma unroll
            for (int hf = 0; hf < 2; hf++)
                rmax[wc * 128 + wr * 64 + i * 16 + qrow + hf * 8] = rm[i][hf];
    __syncthreads();

    float rs[4][2];
#pragma unroll
    for (int i = 0; i < 4; i++)
#pragma unroll
        for (int hf = 0; hf < 2; hf++) {
            const int r = wr * 64 + i * 16 + qrow + hf * 8;
            const float m = fmaxf(rmax[r], rmax[128 + r]);
            float s = 0.0f;
#pragma unroll
            for (int j = 0; j < 5; j++) {
                acc[i][j][hf * 2]     = __expf(acc[i][j][hf * 2]     - m);
                acc[i][j][hf * 2 + 1] = __expf(acc[i][j][hf * 2 + 1] - m);
                s += acc[i][j][hf * 2] + acc[i][j][hf * 2 + 1];
            }
            s += __shfl_xor_sync(0xffffffffu, s, 1);
            s += __shfl_xor_sync(0xffffffffu, s, 2);
            rs[i][hf] = s;
        }
    if ((lane & 3) == 0)
#pragma unroll
        for (int i = 0; i < 4; i++)
#pragma unroll
            for (int hf = 0; hf < 2; hf++)
                rsum[wc * 128 + wr * 64 + i * 16 + qrow + hf * 8] = rs[i][hf];
    __syncthreads();

#pragma unroll
    for (int i = 0; i < 4; i++)
#pragma unroll
        for (int hf = 0; hf < 2; hf++) {
            const int r = wr * 64 + i * 16 + qrow + hf * 8;
            const float inv = 1.0f / (rsum[r] + rsum[128 + r]);
#pragma unroll
            for (int j = 0; j < 5; j++) {
                const int c0 = wc * 40 + j * 8 + qcol;
                const float p0 = acc[i][j][hf * 2] * inv;
                const float p1 = acc[i][j][hf * 2 + 1] * inv;
                __nv_bfloat16 h0 = __float2bfloat16(p0);
                __nv_bfloat16 h1 = __float2bfloat16(p1);
                *(__nv_bfloat162*)(smem + AT_P + r * 176 + c0 * 2) =
                    __halves2bfloat162(h0, h1);
                *(__nv_bfloat162*)(smem + AT_P + AT_PBUF + r * 176 + c0 * 2) =
                    __halves2bfloat162(
                        __float2bfloat16(p0 - __bfloat162float(h0)),
                        __float2bfloat16(p1 - __bfloat162float(h1)));
            }
        }
    cp_wait<0>();
    __syncthreads();

    float acc2[4][4][4];
#pragma unroll
    for (int i = 0; i < 4; i++)
#pragma unroll
        for (int j = 0; j < 4; j++)
#pragma unroll
            for (int e = 0; e < 4; e++) acc2[i][j][e] = 0.0f;

#pragma unroll
    for (int p = 0; p < 3; p++) {
        const uint32_t pb = sbase + AT_P + ((p == 2) ? AT_PBUF : 0);
        const uint32_t vb = sbase + ((p == 1) ? AT_VBUF : 0);
#pragma unroll
        for (int ks = 0; ks < 5; ks++) {
            uint32_t af[4][4], bf[4][2];
#pragma unroll
            for (int i = 0; i < 4; i++)
                ldmatrix_x4(af[i], pb + (wr * 64 + i * 16 + a_row_off) * 176
                                      + ks * 32 + a_k_off);
#pragma unroll
            for (int j = 0; j < 4; j++)
                ldmatrix_x2(bf[j], vb + (wc * 32 + j * 8 + r8) * 176
                                      + ks * 32 + (g & 1) * 16);
#pragma unroll
            for (int i = 0; i < 4; i++)
#pragma unroll
                for (int j = 0; j < 4; j++)
                    mma16816(acc2[i][j], af[i], bf[j]);
        }
    }

#pragma unroll
    for (int i = 0; i < 4; i++) {
        const int n0 = nbase + wr * 64 + i * 16 + qrow;
#pragma unroll
        for (int j = 0; j < 4; j++) {
            const int c0 = wc * 32 + j * 8 + qcol;
            const size_t i0 = (size_t)(b * N_SZ + n0) * INNER + h * CDIM + c0;
            *(__half2*)(aoh + i0) =
                __floats2half2_rn(acc2[i][j][0], acc2[i][j][1]);
            *(__half2*)(aoh + i0 + (size_t)8 * INNER) =
                __floats2half2_rn(acc2[i][j][2], acc2[i][j][3]);
        }
    }
}

// ---------------------------------------------------------------------------
// Launch (4 kernels total)
// ---------------------------------------------------------------------------
extern "C" void kernel_launch(void* const* d_in, const int* in_sizes, int n_in,
                              void* d_out, int out_size)
{
    const float* x    = (const float*)d_in[0];
    const float* key  = (const float*)d_in[1];
    const float* val  = (const float*)d_in[2];
    const int*   mask = (const int*)d_in[3];
    const float* box  = (const float*)d_in[4];
    // d_in[5] road map: softmax-invariant, unused
    const float* Wq   = (const float*)d_in[6];
    const float* Wk   = (const float*)d_in[7];
    const float* Wv   = (const float*)d_in[8];
    const float* Wo   = (const float*)d_in[9];
    const float* bo   = (const float*)d_in[10];
    float*       out  = (float*)d_out;

    __half *xh, *kh, *vh, *wqh, *wql, *wkh, *wkl, *wvh, *wvl, *woh, *wol, *aoh;
    __nv_bfloat16 *qhi, *qlo, *kphi, *kplo, *vthi, *vtlo;
    cudaGetSymbolAddress((void**)&xh, g_xh);
    cudaGetSymbolAddress((void**)&kh, g_kh);
    cudaGetSymbolAddress((void**)&vh, g_vh);
    cudaGetSymbolAddress((void**)&wqh, g_wqh); cudaGetSymbolAddress((void**)&wql, g_wql);
    cudaGetSymbolAddress((void**)&wkh, g_wkh); cudaGetSymbolAddress((void**)&wkl, g_wkl);
    cudaGetSymbolAddress((void**)&wvh, g_wvh); cudaGetSymbolAddress((void**)&wvl, g_wvl);
    cudaGetSymbolAddress((void**)&woh, g_woh); cudaGetSymbolAddress((void**)&wol, g_wol);
    cudaGetSymbolAddress((void**)&aoh, g_aoh);
    cudaGetSymbolAddress((void**)&qhi, g_qhi);   cudaGetSymbolAddress((void**)&qlo, g_qlo);
    cudaGetSymbolAddress((void**)&kphi, g_kphi); cudaGetSymbolAddress((void**)&kplo, g_kplo);
    cudaGetSymbolAddress((void**)&vthi, g_vthi); cudaGetSymbolAddress((void**)&vtlo, g_vtlo);

    constexpr int SMEM_G = NSTAGE * 2 * STAGE_B;   // 81920
    cudaFuncSetAttribute(gemm_proj, cudaFuncAttributeMaxDynamicSharedMemorySize, SMEM_G);
    cudaFuncSetAttribute(gemm_out,  cudaFuncAttributeMaxDynamicSharedMemorySize, SMEM_G);
    cudaFuncSetAttribute(attn_fused, cudaFuncAttributeMaxDynamicSharedMemorySize, AT_SMEM);

    // 1) all splits in one launch
    split_all<<<(S7 + 255) / 256, 256>>>(
        x, key, val, Wq, Wk, Wv, Wo,
        xh, kh, vh, wqh, wql, wkh, wkl, wvh, wvl, woh, wol);

    // 2) all three projections in one launch (z: 0=Q, 1=K, 2=V), fp16 2-pass
    gemm_proj<<<dim3(INNER / 128, ROWS_Q / 128, 3), 128, SMEM_G>>>(
        xh, kh, vh, wqh, wql, wkh, wkl, wvh, wvl,
        qhi, qlo, kphi, kplo, vthi, vtlo);

    // 3) fused attention (bf16 3-pass, ao out as fp16)
    attn_fused<<<dim3(N_SZ / 128, B_SZ * HEADS), 128, AT_SMEM>>>(
        qhi, qlo, kphi, kplo, vthi, vtlo, mask, box, aoh);

    // 4) output projection + bias, fp16 2-pass
    gemm_out<<<dim3((QD + 127) / 128, ROWS_Q / 128), 128, SMEM_G>>>(
        aoh, woh, wol, bo, out);
}

// round 10
// speedup vs baseline: 2.2823x; 1.6991x over previous
#include <cuda_runtime.h>
#include <cuda_bf16.h>
#include <cuda_fp16.h>
#include <cstdint>

// ---------------------------------------------------------------------------
// CrossAttention. R10: FULL fp16 1-pass on all tensor ops (fp32 accum).
// mma.sync accumulates exactly in fp32 — error = input quantization only.
// Calibrated error budget: ~11 fp16 roundings x 1.45e-4 ~ 4.8e-4 < 1e-3.
// ---------------------------------------------------------------------------

#define B_SZ   32
#define N_SZ   1536
#define M_SZ   80
#define HEADS  8
#define CDIM   64
#define INNER  512
#define QD     320
#define KD     768
#define ROWS_Q (B_SZ * N_SZ)     // 49152
#define ROWS_K (B_SZ * M_SZ)     // 2560
#define SCALE  0.125f
#define LAMDA1 5.0f
#define BIGNEG (-3.402823466e38f)

// ---------------- scratch (device globals; allocation forbidden) -----------
__device__ __half g_xh[ROWS_Q * QD];
__device__ __half g_kh[ROWS_K * KD];
__device__ __half g_vh[ROWS_K * KD];
__device__ __half g_wqh[INNER * QD];
__device__ __half g_wkh[INNER * KD];
__device__ __half g_wvh[INNER * KD];
__device__ __half g_woh[QD * INNER];
__device__ __half g_q [ROWS_Q * INNER];
__device__ __half g_kp[ROWS_K * INNER];
__device__ __half g_vt[ROWS_K * INNER];   // [bh][c][m]
__device__ __half g_ao[ROWS_Q * INNER];

// ---------------------------------------------------------------------------
// primitives
// ---------------------------------------------------------------------------
__device__ __forceinline__ uint32_t smem_u32(const void* p) {
    uint32_t a;
    asm("{ .reg .u64 t; cvta.to.shared.u64 t, %1; cvt.u32.u64 %0, t; }"
        : "=r"(a) : "l"(p));
    return a;
}
__device__ __forceinline__ void cp_async16(uint32_t dst, const void* src, uint32_t sz) {
    asm volatile("cp.async.cg.shared.global [%0], [%1], 16, %2;"
                 :: "r"(dst), "l"(src), "r"(sz));
}
__device__ __forceinline__ void cp_commit() { asm volatile("cp.async.commit_group;"); }
template <int N>
__device__ __forceinline__ void cp_wait() {
    asm volatile("cp.async.wait_group %0;" :: "n"(N));
}
__device__ __forceinline__ void ldmatrix_x4(uint32_t* r, uint32_t addr) {
    asm volatile("ldmatrix.sync.aligned.m8n8.x4.shared.b16 {%0,%1,%2,%3}, [%4];"
                 : "=r"(r[0]), "=r"(r[1]), "=r"(r[2]), "=r"(r[3]) : "r"(addr));
}
__device__ __forceinline__ void ldmatrix_x2(uint32_t* r, uint32_t addr) {
    asm volatile("ldmatrix.sync.aligned.m8n8.x2.shared.b16 {%0,%1}, [%2];"
                 : "=r"(r[0]), "=r"(r[1]) : "r"(addr));
}
__device__ __forceinline__ void mma16816h(float* d, const uint32_t* a, const uint32_t* b) {
    asm volatile(
        "mma.sync.aligned.m16n8k16.row.col.f32.f16.f16.f32 "
        "{%0,%1,%2,%3}, {%4,%5,%6,%7}, {%8,%9}, {%0,%1,%2,%3};"
        : "+f"(d[0]), "+f"(d[1]), "+f"(d[2]), "+f"(d[3])
        : "r"(a[0]), "r"(a[1]), "r"(a[2]), "r"(a[3]), "r"(b[0]), "r"(b[1]));
}
__device__ __forceinline__ void h_store2(__half* dst, size_t idx, float a, float b) {
    *(__half2*)(dst + idx) = __floats2half2_rn(a, b);
}
#define SWZ(off) ((off) ^ (((off) >> 3) & 0x70))

// ---------------------------------------------------------------------------
// mega-split: all 7 fp32 tensors -> fp16 in one launch.
// ---------------------------------------------------------------------------
#define N4_X   (ROWS_Q * QD / 4)
#define N4_KEY (ROWS_K * KD / 4)
#define N4_VAL (ROWS_K * KD / 4)
#define N4_WQ  (INNER * QD / 4)
#define N4_WK  (INNER * KD / 4)
#define N4_WV  (INNER * KD / 4)
#define N4_WO  (QD * INNER / 4)
#define S1 (N4_X)
#define S2 (S1 + N4_KEY)
#define S3 (S2 + N4_VAL)
#define S4 (S3 + N4_WQ)
#define S5 (S4 + N4_WK)
#define S6 (S5 + N4_WV)
#define S7 (S6 + N4_WO)

__global__ void __launch_bounds__(256)
split_all(const float* __restrict__ x,   const float* __restrict__ key,
          const float* __restrict__ val, const float* __restrict__ wq,
          const float* __restrict__ wk,  const float* __restrict__ wv,
          const float* __restrict__ wo,
          __half* __restrict__ xh, __half* __restrict__ kh, __half* __restrict__ vh,
          __half* __restrict__ wqh, __half* __restrict__ wkh,
          __half* __restrict__ wvh, __half* __restrict__ woh)
{
    const int i = blockIdx.x * blockDim.x + threadIdx.x;
    if (i >= S7) return;

    const float* src; __half* dst; int off;
    if      (i < S1) { src = x;   dst = xh;  off = i;      }
    else if (i < S2) { src = key; dst = kh;  off = i - S1; }
    else if (i < S3) { src = val; dst = vh;  off = i - S2; }
    else if (i < S4) { src = wq;  dst = wqh; off = i - S3; }
    else if (i < S5) { src = wk;  dst = wkh; off = i - S4; }
    else if (i < S6) { src = wv;  dst = wvh; off = i - S5; }
    else             { src = wo;  dst = woh; off = i - S6; }

    float4 v = ((const float4*)src)[off];
    h_store2(dst, (size_t)off * 4,     v.x, v.y);
    h_store2(dst, (size_t)off * 4 + 2, v.z, v.w);
}

// ---------------------------------------------------------------------------
// fp16 1-pass GEMM core (BM=BN=128, BK=32, 4 warps 2x2, 64x64 warp tiles,
// 4-stage cp.async, single barrier per iter).
// ---------------------------------------------------------------------------
#define STAGE_B (128 * 40 * 2)   // 10240 bytes per operand per stage
#define NSTAGE  4
#define KCHUNK  32

struct GemmCore {
    uint32_t sbase;
    int tid, wid, lane, wm, wn;
    int g, r8, a_row_off, a_k_off, bx_row_off, bx_k_off;

    __device__ __forceinline__ void init(uint32_t sb, int t) {
        sbase = sb; tid = t;
        wid = t >> 5; lane = t & 31;
        wm = wid >> 1; wn = wid & 1;
        g = lane >> 3; r8 = lane & 7;
        a_row_off = (g & 1) * 8 + r8;
        a_k_off   = (g >> 1) * 16;
        bx_row_off = (g >> 1) * 8 + r8;
        bx_k_off   = (g & 1) * 16;
    }

    template <bool GUARD>
    __device__ __forceinline__ void load_stage(
        const __half* A, const __half* B,
        int rbase, int cbase, int cols, int K, int it, int stage)
    {
        const int kb = it * KCHUNK;
        const uint32_t abase = sbase + stage * 2 * STAGE_B;
        const uint32_t bbase = abase + STAGE_B;
#pragma unroll
        for (int t = 0; t < 4; t++) {
            const int task = t * 128 + tid;
            const int row  = task >> 2;
            const int ch   = task & 3;
            cp_async16(abase + row * 80 + ch * 16,
                       A + (size_t)(rbase + row) * K + kb + ch * 8, 16);
        }
#pragma unroll
        for (int t = 0; t < 4; t++) {
            const int task = t * 128 + tid;
            const int row  = task >> 2;
            const int ch   = task & 3;
            if (GUARD) {
                const int col   = cbase + row;
                const int valid = (col < cols);
                cp_async16(bbase + row * 80 + ch * 16,
                           B + (size_t)(valid ? col : 0) * K + kb + ch * 8,
                           valid ? 16u : 0u);
            } else {
                cp_async16(bbase + row * 80 + ch * 16,
                           B + (size_t)(cbase + row) * K + kb + ch * 8, 16);
            }
        }
        cp_commit();
    }

    template <bool GUARD>
    __device__ __forceinline__ void run(
        float acc[4][8][4],
        const __half* A, const __half* B,
        int rbase, int cbase, int cols, int K)
    {
        const int KT = K / KCHUNK;     // >= 10 for all calls
        load_stage<GUARD>(A, B, rbase, cbase, cols, K, 0, 0);
        load_stage<GUARD>(A, B, rbase, cbase, cols, K, 1, 1);
        load_stage<GUARD>(A, B, rbase, cbase, cols, K, 2, 2);

        for (int it = 0; it < KT; it++) {
            cp_wait<2>();
            __syncthreads();
            if (it + 3 < KT)
                load_stage<GUARD>(A, B, rbase, cbase, cols, K,
                                  it + 3, (it + 3) & (NSTAGE - 1));
            else cp_commit();

            const int stage = it & (NSTAGE - 1);
            const uint32_t sA = sbase + stage * 2 * STAGE_B;
            const uint32_t sB = sA + STAGE_B;
#pragma unroll
            for (int s = 0; s < 2; s++) {
                uint32_t afrag[4][4];
                uint32_t bfrag[8][2];
#pragma unroll
                for (int i = 0; i < 4; i++)
                    ldmatrix_x4(afrag[i],
                        sA + (wm * 64 + i * 16 + a_row_off) * 80 + s * 32 + a_k_off);
#pragma unroll
                for (int jj = 0; jj < 4; jj++) {
                    uint32_t r[4];
                    ldmatrix_x4(r,
                        sB + (wn * 64 + jj * 16 + bx_row_off) * 80 + s * 32 + bx_k_off);
                    bfrag[jj * 2][0]     = r[0]; bfrag[jj * 2][1]     = r[1];
                    bfrag[jj * 2 + 1][0] = r[2]; bfrag[jj * 2 + 1][1] = r[3];
                }
#pragma unroll
                for (int i = 0; i < 4; i++)
#pragma unroll
                    for (int j = 0; j < 8; j++)
                        mma16816h(acc[i][j], afrag[i], bfrag[j]);
            }
        }
    }
};

// ---------------------------------------------------------------------------
// merged projection kernel: blockIdx.z = 0:Q(scaled), 1:K, 2:V(transposed).
// ---------------------------------------------------------------------------
__global__ void __launch_bounds__(128, 2)
gemm_proj(const __half* __restrict__ xh, const __half* __restrict__ kh,
          const __half* __restrict__ vh,
          const __half* __restrict__ wqh, const __half* __restrict__ wkh,
          const __half* __restrict__ wvh,
          __half* __restrict__ q, __half* __restrict__ kp, __half* __restrict__ vt)
{
    const int z = blockIdx.z;
    if (z > 0 && blockIdx.y >= ROWS_K / 128) return;

    const __half *A, *B;
    __half* C;
    int K;
    float ascale = 1.0f;
    if (z == 0)      { A = xh; B = wqh; C = q;  K = QD; ascale = SCALE; }
    else if (z == 1) { A = kh; B = wkh; C = kp; K = KD; }
    else             { A = vh; B = wvh; C = vt; K = KD; }

    extern __shared__ char smem[];
    GemmCore core;
    core.init(smem_u32(smem), threadIdx.x);

    const int rbase = blockIdx.y * 128;
    const int cbase = blockIdx.x * 128;

    float acc[4][8][4];
#pragma unroll
    for (int i = 0; i < 4; i++)
#pragma unroll
        for (int j = 0; j < 8; j++)
#pragma unroll
            for (int e = 0; e < 4; e++) acc[i][j][e] = 0.0f;

    core.run<false>(acc, A, B, rbase, cbase, INNER, K);

    const int qrow = core.lane >> 2;
    const int qcol = (core.lane & 3) * 2;
    if (z < 2) {
#pragma unroll
        for (int i = 0; i < 4; i++) {
            const int row0 = rbase + core.wm * 64 + i * 16 + qrow;
#pragma unroll
            for (int j = 0; j < 8; j++) {
                const int col0 = cbase + core.wn * 64 + j * 8 + qcol;
                h_store2(C, (size_t)row0 * INNER + col0,
                         acc[i][j][0] * ascale, acc[i][j][1] * ascale);
                h_store2(C, (size_t)(row0 + 8) * INNER + col0,
                         acc[i][j][2] * ascale, acc[i][j][3] * ascale);
            }
        }
    } else {
#pragma unroll
        for (int i = 0; i < 4; i++) {
            const int row0 = rbase + core.wm * 64 + i * 16 + qrow;
#pragma unroll
            for (int j = 0; j < 8; j++) {
                const int col0 = cbase + core.wn * 64 + j * 8 + qcol;
#pragma unroll
                for (int rr = 0; rr < 2; rr++) {
                    const int r = row0 + rr * 8;
                    const int bb = r / M_SZ;
                    const int m  = r - bb * M_SZ;
#pragma unroll
                    for (int cc = 0; cc < 2; cc++) {
                        const int col = col0 + cc;
                        const int idx = (bb * HEADS + (col >> 6)) * CDIM + (col & 63);
                        C[(size_t)idx * M_SZ + m] =
                            __float2half_rn(acc[i][j][rr * 2 + cc]);
                    }
                }
            }
        }
    }
}

// ---------------------------------------------------------------------------
// output projection: out = ao @ Wo^T + bo (cols=320, guard needed)
// ---------------------------------------------------------------------------
__global__ void __launch_bounds__(128, 2)
gemm_out(const __half* __restrict__ A, const __half* __restrict__ B,
         const float* __restrict__ bias, float* __restrict__ Cf)
{
    extern __shared__ char smem[];
    GemmCore core;
    core.init(smem_u32(smem), threadIdx.x);

    const int rbase = blockIdx.y * 128;
    const int cbase = blockIdx.x * 128;

    float acc[4][8][4];
#pragma unroll
    for (int i = 0; i < 4; i++)
#pragma unroll
        for (int j = 0; j < 8; j++)
#pragma unroll
            for (int e = 0; e < 4; e++) acc[i][j][e] = 0.0f;

    core.run<true>(acc, A, B, rbase, cbase, QD, INNER);

    const int qrow = core.lane >> 2;
    const int qcol = (core.lane & 3) * 2;
#pragma unroll
    for (int i = 0; i < 4; i++) {
        const int row0 = rbase + core.wm * 64 + i * 16 + qrow;
#pragma unroll
        for (int j = 0; j < 8; j++) {
            const int col0 = cbase + core.wn * 64 + j * 8 + qcol;
            if (col0 >= QD) continue;
            const float b0 = bias[col0], b1 = bias[col0 + 1];
            *(float2*)(Cf + (size_t)row0 * QD + col0) =
                make_float2(acc[i][j][0] + b0, acc[i][j][1] + b1);
            *(float2*)(Cf + (size_t)(row0 + 8) * QD + col0) =
                make_float2(acc[i][j][2] + b0, acc[i][j][3] + b1);
        }
    }
}

// ---------------------------------------------------------------------------
// Fused attention, fp16 1-pass: S = QK^T (q pre-scaled), mask + box bias,
// softmax, P fp16 SMEM-resident, O = P*Vt -> ao fp16.
// SMEM: [0,16384) Q (swizzled 128B rows)        -> reused for Vt (pitch 176)
//       [16384,26624) K (swizzled)              -> reused by P head
//       [26624,67584) box fp32 (128x320B)       -> reused by P tail
//       [67584,69632) rmax/rsum ; [69632,69952) mask
//       P at 16384..38912 (pitch 176, fp16)
// ---------------------------------------------------------------------------
#define AT_Q    0
#define AT_K    16384
#define AT_BOX  26624
#define AT_RED  67584
#define AT_MASK 69632
#define AT_V    0
#define AT_P    16384
#define AT_SMEM 69952

__global__ void __launch_bounds__(128, 2)
attn_fused(const __half* __restrict__ q, const __half* __restrict__ kp,
           const __half* __restrict__ vt,
           const int* __restrict__ mask, const float* __restrict__ box,
           __half* __restrict__ ao)
{
    extern __shared__ char smem[];
    const uint32_t sbase = smem_u32(smem);
    const int tid  = threadIdx.x;
    const int wid  = tid >> 5;
    const int lane = tid & 31;
    const int wr   = wid >> 1;
    const int wc   = wid & 1;
    const int bh   = blockIdx.y;
    const int b    = bh >> 3, h = bh & 7;
    const int nbase = blockIdx.x * 128;

    int* smask = (int*)(smem + AT_MASK);
    if (tid < M_SZ) smask[tid] = mask[b * M_SZ + tid];

    // Q: 128 rows x 8 chunks (64 fp16 = 128B/row, swizzled)
#pragma unroll
    for (int u = 0; u < 8; u++) {
        const int task = u * 128 + tid;
        const int row  = task >> 3, ch = task & 7;
        cp_async16(sbase + AT_Q + SWZ(row * 128 + ch * 16),
                   q + (size_t)(b * N_SZ + nbase + row) * INNER + h * CDIM + ch * 8, 16);
    }
    // K: 80 rows x 8 chunks
#pragma unroll
    for (int u = 0; u < 5; u++) {
        const int task = u * 128 + tid;
        const int row  = task >> 3, ch = task & 7;
        cp_async16(sbase + AT_K + SWZ(row * 128 + ch * 16),
                   kp + (size_t)(b * M_SZ + row) * INNER + h * CDIM + ch * 8, 16);
    }
    // box: 128 rows x 20 chunks (80 fp32)
#pragma unroll
    for (int u = 0; u < 20; u++) {
        const int task = u * 128 + tid;
        const int row  = task / 20, ch = task - row * 20;
        cp_async16(sbase + AT_BOX + row * 320 + ch * 16,
                   box + (size_t)(b * N_SZ + nbase + row) * M_SZ + ch * 4, 16);
    }
    cp_commit();
    cp_wait<0>();
    __syncthreads();

    const int g  = lane >> 3;
    const int r8 = lane & 7;
    const int a_row_off = (g & 1) * 8 + r8;
    const int a_k_off   = (g >> 1) * 16;

    // ---- QK, single fp16 pass (K = 64 = 4 x k16) ----
    float acc[4][5][4];
#pragma unroll
    for (int i = 0; i < 4; i++)
#pragma unroll
        for (int j = 0; j < 5; j++)
#pragma unroll
            for (int e = 0; e < 4; e++) acc[i][j][e] = 0.0f;

#pragma unroll
    for (int ks = 0; ks < 4; ks++) {
        uint32_t af[4][4], bf[5][2];
#pragma unroll
        for (int i = 0; i < 4; i++)
            ldmatrix_x4(af[i], sbase + AT_Q + SWZ((wr * 64 + i * 16 + a_row_off) * 128
                                                  + ks * 32 + a_k_off));
#pragma unroll
        for (int j = 0; j < 5; j++)
            ldmatrix_x2(bf[j], sbase + AT_K + SWZ((wc * 40 + j * 8 + r8) * 128
                                                  + ks * 32 + (g & 1) * 16));
#pragma unroll
        for (int i = 0; i < 4; i++)
#pragma unroll
            for (int j = 0; j < 5; j++)
                mma16816h(acc[i][j], af[i], bf[j]);
    }
    __syncthreads();    // all warps done reading Q/K smem

    // ---- Vt loads into Q region (overlap softmax) ----
#pragma unroll
    for (int u = 0; u < 5; u++) {
        const int task = u * 128 + tid;
        const int row  = task / 10, ch = task - row * 10;
        cp_async16(sbase + AT_V + row * 176 + ch * 16,
                   vt + ((size_t)bh * CDIM + row) * M_SZ + ch * 8, 16);
    }
    cp_commit();

    // ---- mask + box bias (consumes box smem before P overwrites it) ----
    const float* boxS = (const float*)(smem + AT_BOX);
    const int qrow = lane >> 2;
    const int qcol = (lane & 3) * 2;
#pragma unroll
    for (int i = 0; i < 4; i++)
#pragma unroll
        for (int j = 0; j < 5; j++)
#pragma unroll
            for (int e = 0; e < 4; e++) {
                const int r = wr * 64 + i * 16 + qrow + (e >> 1) * 8;
                const int c = wc * 40 + j * 8 + qcol + (e & 1);
                acc[i][j][e] = smask[c]
                    ? acc[i][j][e] + LAMDA1 * boxS[r * 80 + c] : BIGNEG;
            }

    // ---- softmax ----
    float* rmax = (float*)(smem + AT_RED);
    float* rsum = rmax + 256;
    float rm[4][2];
#pragma unroll
    for (int i = 0; i < 4; i++)
#pragma unroll
        for (int hf = 0; hf < 2; hf++) {
            float m = BIGNEG;
#pragma unroll
            for (int j = 0; j < 5; j++)
                m = fmaxf(m, fmaxf(acc[i][j][hf * 2], acc[i][j][hf * 2 + 1]));
            m = fmaxf(m, __shfl_xor_sync(0xffffffffu, m, 1));
            m = fmaxf(m, __shfl_xor_sync(0xffffffffu, m, 2));
            rm[i][hf] = m;
        }
    if ((lane & 3) == 0)
#pragma unroll
        for (int i = 0; i < 4; i++)
#pragma unroll
            for (int hf = 0; hf < 2; hf++)
                rmax[wc * 128 + wr * 64 + i * 16 + qrow + hf * 8] = rm[i][hf];
    __syncthreads();

    float rs[4][2];
#pragma unroll
    for (int i = 0; i < 4; i++)
#pragma unroll
        for (int hf = 0; hf < 2; hf++) {
            const int r = wr * 64 + i * 16 + qrow + hf * 8;
            const float m = fmaxf(rmax[r], rmax[128 + r]);
            float s = 0.0f;
#pragma unroll
            for (int j = 0; j < 5; j++) {
                acc[i][j][hf * 2]     = __expf(acc[i][j][hf * 2]     - m);
                acc[i][j][hf * 2 + 1] = __expf(acc[i][j][hf * 2 + 1] - m);
                s += acc[i][j][hf * 2] + acc[i][j][hf * 2 + 1];
            }
            s += __shfl_xor_sync(0xffffffffu, s, 1);
            s += __shfl_xor_sync(0xffffffffu, s, 2);
            rs[i][hf] = s;
        }
    if ((lane & 3) == 0)
#pragma unroll
        for (int i = 0; i < 4; i++)
#pragma unroll
            for (int hf = 0; hf < 2; hf++)
                rsum[wc * 128 + wr * 64 + i * 16 + qrow + hf * 8] = rs[i][hf];
    __syncthreads();

    // ---- normalize, store P fp16 (into K/box region) ----
#pragma unroll
    for (int i = 0; i < 4; i++)
#pragma unroll
        for (int hf = 0; hf < 2; hf++) {
            const int r = wr * 64 + i * 16 + qrow + hf * 8;
            const float inv = 1.0f / (rsum[r] + rsum[128 + r]);
#pragma unroll
            for (int j = 0; j < 5; j++) {
                const int c0 = wc * 40 + j * 8 + qcol;
                *(__half2*)(smem + AT_P + r * 176 + c0 * 2) =
                    __floats2half2_rn(acc[i][j][hf * 2] * inv,
                                      acc[i][j][hf * 2 + 1] * inv);
            }
        }
    cp_wait<0>();
    __syncthreads();

    // ---- PV, single fp16 pass (K = 80 = 5 x k16) ----
    float acc2[4][4][4];
#pragma unroll
    for (int i = 0; i < 4; i++)
#pragma unroll
        for (int j = 0; j < 4; j++)
#pragma unroll
            for (int e = 0; e < 4; e++) acc2[i][j][e] = 0.0f;

#pragma unroll
    for (int ks = 0; ks < 5; ks++) {
        uint32_t af[4][4], bf[4][2];
#pragma unroll
        for (int i = 0; i < 4; i++)
            ldmatrix_x4(af[i], sbase + AT_P + (wr * 64 + i * 16 + a_row_off) * 176
                                  + ks * 32 + a_k_off);
#pragma unroll
        for (int j = 0; j < 4; j++)
            ldmatrix_x2(bf[j], sbase + AT_V + (wc * 32 + j * 8 + r8) * 176
                                  + ks * 32 + (g & 1) * 16);
#pragma unroll
        for (int i = 0; i < 4; i++)
#pragma unroll
            for (int j = 0; j < 4; j++)
                mma16816h(acc2[i][j], af[i], bf[j]);
    }

    // ---- ao fp16 out ----
#pragma unroll
    for (int i = 0; i < 4; i++) {
        const int n0 = nbase + wr * 64 + i * 16 + qrow;
#pragma unroll
        for (int j = 0; j < 4; j++) {
            const int c0 = wc * 32 + j * 8 + qcol;
            const size_t i0 = (size_t)(b * N_SZ + n0) * INNER + h * CDIM + c0;
            *(__half2*)(ao + i0) =
                __floats2half2_rn(acc2[i][j][0], acc2[i][j][1]);
            *(__half2*)(ao + i0 + (size_t)8 * INNER) =
                __floats2half2_rn(acc2[i][j][2], acc2[i][j][3]);
        }
    }
}

// ---------------------------------------------------------------------------
// Launch (4 kernels total)
// ---------------------------------------------------------------------------
extern "C" void kernel_launch(void* const* d_in, const int* in_sizes, int n_in,
                              void* d_out, int out_size)
{
    const float* x    = (const float*)d_in[0];
    const float* key  = (const float*)d_in[1];
    const float* val  = (const float*)d_in[2];
    const int*   mask = (const int*)d_in[3];
    const float* box  = (const float*)d_in[4];
    // d_in[5] road map: softmax-invariant, unused
    const float* Wq   = (const float*)d_in[6];
    const float* Wk   = (const float*)d_in[7];
    const float* Wv   = (const float*)d_in[8];
    const float* Wo   = (const float*)d_in[9];
    const float* bo   = (const float*)d_in[10];
    float*       out  = (float*)d_out;

    __half *xh, *kh, *vh, *wqh, *wkh, *wvh, *woh, *q, *kp, *vt, *ao;
    cudaGetSymbolAddress((void**)&xh, g_xh);
    cudaGetSymbolAddress((void**)&kh, g_kh);
    cudaGetSymbolAddress((void**)&vh, g_vh);
    cudaGetSymbolAddress((void**)&wqh, g_wqh);
    cudaGetSymbolAddress((void**)&wkh, g_wkh);
    cudaGetSymbolAddress((void**)&wvh, g_wvh);
    cudaGetSymbolAddress((void**)&woh, g_woh);
    cudaGetSymbolAddress((void**)&q,  g_q);
    cudaGetSymbolAddress((void**)&kp, g_kp);
    cudaGetSymbolAddress((void**)&vt, g_vt);
    cudaGetSymbolAddress((void**)&ao, g_ao);

    constexpr int SMEM_G = NSTAGE * 2 * STAGE_B;   // 81920
    cudaFuncSetAttribute(gemm_proj, cudaFuncAttributeMaxDynamicSharedMemorySize, SMEM_G);
    cudaFuncSetAttribute(gemm_out,  cudaFuncAttributeMaxDynamicSharedMemorySize, SMEM_G);
    cudaFuncSetAttribute(attn_fused, cudaFuncAttributeMaxDynamicSharedMemorySize, AT_SMEM);

    // 1) all fp32 -> fp16 conversions in one launch
    split_all<<<(S7 + 255) / 256, 256>>>(
        x, key, val, Wq, Wk, Wv, Wo, xh, kh, vh, wqh, wkh, wvh, woh);

    // 2) all three projections in one launch (z: 0=Q, 1=K, 2=V), fp16 1-pass
    gemm_proj<<<dim3(INNER / 128, ROWS_Q / 128, 3), 128, SMEM_G>>>(
        xh, kh, vh, wqh, wkh, wvh, q, kp, vt);

    // 3) fused attention, fp16 1-pass
    attn_fused<<<dim3(N_SZ / 128, B_SZ * HEADS), 128, AT_SMEM>>>(
        q, kp, vt, mask, box, ao);

    // 4) output projection + bias, fp16 1-pass
    gemm_out<<<dim3((QD + 127) / 128, ROWS_Q / 128), 128, SMEM_G>>>(
        ao, woh, bo, out);
}